// round 14
// baseline (speedup 1.0000x reference)
// R14: identical to R13 (re-bench after infra failure; audit found no defects)
#include <cuda_runtime.h>

#define B_      16
#define D_      64
#define N_      256
#define E_      64
#define HID_    128
#define OUT_    64
#define IN_     192
#define R_PAIRS 32640
#define HB      4          // h per block
#define VSTRIDE 6          // us/vs row stride in floats (4 h + 2 pad, even -> 8B ull ok)

typedef unsigned long long ull;

// Cross-block scratch
__device__ float    g_S[B_ * HID_];
__device__ unsigned g_done[B_];

// ---------------- packed f32x2 helpers ----------------
__device__ __forceinline__ void fma2(ull& acc, ull w, ull x) {
    asm("fma.rn.f32x2 %0, %1, %2, %3;" : "=l"(acc) : "l"(w), "l"(x), "l"(acc));
}
__device__ __forceinline__ ull pack2(float a, float b) {
    ull r;
    asm("mov.b64 %0, {%1, %2};" : "=l"(r) : "f"(a), "f"(b));
    return r;
}
__device__ __forceinline__ float lo2(ull v) {
    return __uint_as_float((unsigned)(v & 0xffffffffu));
}
__device__ __forceinline__ float hi2(ull v) {
    return __uint_as_float((unsigned)(v >> 32));
}
__device__ __forceinline__ ull padd2(ull a, ull b) {
    ull r;
    asm("add.rn.f32x2 %0, %1, %2;" : "=l"(r) : "l"(a), "l"(b));
    return r;
}
__device__ __forceinline__ void addabs2(ull& acc, ull t2, ull v2, ull mask) {
    ull x;
    asm("add.rn.f32x2 %0, %1, %2;" : "=l"(x) : "l"(t2), "l"(v2));
    asm("and.b64 %0, %1, %2;" : "=l"(x) : "l"(x), "l"(mask));
    asm("add.rn.f32x2 %0, %1, %2;" : "=l"(acc) : "l"(acc), "l"(x));
}

// ===========================================================================
// grid = 512 = (b:16, hq:32 -> 4 h each); block = 256 (8 warps), ~17 KB smem.
// ===========================================================================
__global__ __launch_bounds__(256, 4) void fused_kernel(
    const float* __restrict__ x, const float* __restrict__ emb,
    const float* __restrict__ W1, const float* __restrict__ b1,
    const float* __restrict__ W2, const float* __restrict__ b2,
    float* __restrict__ out)
{
    __shared__ __align__(16) ull   wt[HB * 2 * 64];        // dup-packed W1, 4 KB
    __shared__ __align__(8)  float us[N_ * VSTRIDE];       // 6 KB
    __shared__ __align__(8)  float vs[N_ * VSTRIDE];       // 6 KB
    __shared__ __align__(8)  float cs[HB];
    __shared__ float  lr[HB][2];
    __shared__ float2 red[8][2];
    __shared__ __align__(16) float Ss[HID_];
    __shared__ bool lastf;

    const int bx    = blockIdx.x;
    const int hq    = bx & 31;
    const int b     = bx >> 5;
    const int hbase = hq * HB;
    const int tid   = threadIdx.x;
    const int w     = tid >> 5;
    const int lane  = tid & 31;

    // ---- build duplicated W table: wt[hl*128 + ab*64 + d] = (W,W) ----
#pragma unroll
    for (int i = 0; i < 2; ++i) {
        int idx = i * 256 + tid;
        int hl  = idx >> 7;
        int ab  = (idx >> 6) & 1;
        int d   = idx & 63;
        float wv = W1[(hbase + hl) * IN_ + ab * 64 + d];
        wt[idx] = pack2(wv, wv);
    }
    // ---- C for these 4 h ----
    if (tid < HB) {
        int h = hbase + tid;
        const float4* wr = (const float4*)(W1 + h * IN_ + 2 * D_);
        const float4* er = (const float4*)(emb + b * E_);
        float acc = b1[h];
#pragma unroll
        for (int e4 = 0; e4 < E_ / 4; ++e4) {
            float4 ww = wr[e4]; float4 ee = er[e4];
            acc += ww.x * ee.x + ww.y * ee.y + ww.z * ee.z + ww.w * ee.w;
        }
        cs[tid] = acc;
    }
    __syncthreads();

    // ================= Phase A: warp = (hl: w&3, nh: w>>2); 1 h x 128 n ======
    {
        const int hl = w & 3;
        const int nh = w >> 2;
        const int nb = nh * 128 + 4 * lane;        // 4 consecutive n per lane
        const float4* xp = (const float4*)(x + b * D_ * N_ + nb);
        const ulonglong2* wA = (const ulonglong2*)(wt + hl * 128);
        const ulonglong2* wB = (const ulonglong2*)(wt + hl * 128 + 64);

        ull au0 = 0, au1 = 0, av0 = 0, av1 = 0;
#pragma unroll 4
        for (int d2 = 0; d2 < 32; ++d2) {
            float4 xva = xp[(2 * d2) * (N_ / 4)];
            float4 xvb = xp[(2 * d2 + 1) * (N_ / 4)];
            ulonglong2 xa = *reinterpret_cast<ulonglong2*>(&xva);
            ulonglong2 xb = *reinterpret_cast<ulonglong2*>(&xvb);
            ulonglong2 A  = wA[d2];
            ulonglong2 Bv = wB[d2];
            fma2(au0, A.x,  xa.x); fma2(au1, A.x,  xa.y);
            fma2(au0, A.y,  xb.x); fma2(au1, A.y,  xb.y);
            fma2(av0, Bv.x, xa.x); fma2(av1, Bv.x, xa.y);
            fma2(av0, Bv.y, xb.x); fma2(av1, Bv.y, xb.y);
        }

        float u0 = lo2(au0), u1 = hi2(au0), u2 = lo2(au1), u3 = hi2(au1);
        float v0 = lo2(av0), v1 = hi2(av0), v2 = lo2(av1), v3 = hi2(av1);

        us[(nb + 0) * VSTRIDE + hl] = u0;
        us[(nb + 1) * VSTRIDE + hl] = u1;
        us[(nb + 2) * VSTRIDE + hl] = u2;
        us[(nb + 3) * VSTRIDE + hl] = u3;
        vs[(nb + 0) * VSTRIDE + hl] = v0;
        vs[(nb + 1) * VSTRIDE + hl] = v1;
        vs[(nb + 2) * VSTRIDE + hl] = v2;
        vs[(nb + 3) * VSTRIDE + hl] = v3;

        // lin partial for this h over the 4 n owned by this lane
        float nf = (float)nb;
        float lin = u0 * (255.0f - nf)          + v0 * nf
                  + u1 * (254.0f - nf)          + v1 * (nf + 1.0f)
                  + u2 * (253.0f - nf)          + v2 * (nf + 2.0f)
                  + u3 * (252.0f - nf)          + v3 * (nf + 3.0f);
#pragma unroll
        for (int o = 16; o; o >>= 1)
            lin += __shfl_xor_sync(0xffffffffu, lin, o);
        if (lane == 0) lr[hl][nh] = lin;
    }
    __syncthreads();

    // ================= Phase B: warp w -> tiles {2w, 2w+1, 30-2w, 31-2w} =====
    {
        const ull mask = 0x7FFFFFFF7FFFFFFFull;
        const int hp    = lane & 1;               // h-pair 0..1 (covers 4 h)
        const int isub  = (lane >> 1) & 7;        // i within tile
        const int jhalf = lane >> 4;

        ull ccp;
        { float2 c2 = *(const float2*)(cs + 2 * hp); ccp = pack2(c2.x, c2.y); }

        ull acc0 = 0, acc1 = 0, acc2 = 0, acc3 = 0;
#pragma unroll
        for (int rep = 0; rep < 4; ++rep) {
            int tile = (rep == 0) ? 2 * w
                     : (rep == 1) ? 2 * w + 1
                     : (rep == 2) ? 30 - 2 * w
                     :              31 - 2 * w;
            int i0 = tile * 8;
            int i  = i0 + isub;

            ull uu = *(const ull*)(us + i * VSTRIDE + 2 * hp);
            ull tt = padd2(uu, ccp);

            // triangular corner (jhalf 0 lanes only; isub < jj)
            if (jhalf == 0) {
#pragma unroll
                for (int jj = 1; jj < 8; ++jj) {
                    ull vj = *(const ull*)(vs + (i0 + jj) * VSTRIDE + 2 * hp);
                    if (isub < jj) addabs2(acc0, tt, vj, mask);
                }
            }

            int len  = 248 - 8 * tile;            // multiple of 8 (0 for tile 31)
            int half = len >> 1;                  // multiple of 4
            int jlo  = i0 + 8 + jhalf * half;
            int jhi  = jlo + half;
            const float* vb = vs + 2 * hp;
            for (int j = jlo; j < jhi; j += 4) {
                ull v0 = *(const ull*)(vb + (j + 0) * VSTRIDE);
                ull v1 = *(const ull*)(vb + (j + 1) * VSTRIDE);
                ull v2 = *(const ull*)(vb + (j + 2) * VSTRIDE);
                ull v3 = *(const ull*)(vb + (j + 3) * VSTRIDE);
                addabs2(acc0, tt, v0, mask);
                addabs2(acc1, tt, v1, mask);
                addabs2(acc2, tt, v2, mask);
                addabs2(acc3, tt, v3, mask);
            }
        }

        ull s2 = padd2(padd2(acc0, acc1), padd2(acc2, acc3));
        float sx = lo2(s2), sy = hi2(s2);
#pragma unroll
        for (int off = 2; off <= 16; off <<= 1) {
            sx += __shfl_xor_sync(0xffffffffu, sx, off);
            sy += __shfl_xor_sync(0xffffffffu, sy, off);
        }
        if (lane < 2) red[w][lane] = make_float2(sx, sy);
    }
    __syncthreads();

    // ================= combine: S[b][hbase..hbase+3] =================
    if (tid < HB) {
        int h  = tid;
        int hp = h >> 1;
        int c  = h & 1;
        float sabs = 0.0f;
#pragma unroll
        for (int ww = 0; ww < 8; ++ww) {
            float2 r = red[ww][hp];
            sabs += c ? r.y : r.x;
        }
        float lin = lr[h][0] + lr[h][1];
        lin += cs[h] * (float)R_PAIRS;
        g_S[b * HID_ + hbase + h] = 0.5f * (lin + sabs);
    }

    // ================= completion: last of 32 blocks per b does out GEMM =====
    __syncthreads();
    if (tid == 0) {
        __threadfence();
        unsigned v = atomicAdd(&g_done[b], 1u);
        bool last = (v == 31u);
        lastf = last;
        if (last) {
            g_done[b] = 0;         // reset for next graph replay
            __threadfence();
        }
    }
    __syncthreads();

    if (lastf) {
        if (tid < HID_) Ss[tid] = g_S[b * HID_ + tid];
        __syncthreads();
        // 256 threads: o = tid>>2 (64 outputs), 4 lanes x 32 h each
        int o   = tid >> 2;
        int sub = tid & 3;
        const float4* wv = (const float4*)(W2 + o * HID_ + sub * 32);
        const float4* sv = (const float4*)(Ss + sub * 32);
        float acc = 0.0f;
#pragma unroll
        for (int q2 = 0; q2 < 8; ++q2) {
            float4 ww = wv[q2]; float4 ssv = sv[q2];
            acc += ww.x * ssv.x + ww.y * ssv.y + ww.z * ssv.z + ww.w * ssv.w;
        }
        acc += __shfl_xor_sync(0xffffffffu, acc, 1);
        acc += __shfl_xor_sync(0xffffffffu, acc, 2);
        if (sub == 0)
            out[b * OUT_ + o] = acc + (float)R_PAIRS * b2[o];
    }
}

// ---------------------------------------------------------------------------
extern "C" void kernel_launch(void* const* d_in, const int* in_sizes, int n_in,
                              void* d_out, int out_size) {
    const float* x   = (const float*)d_in[0];
    const float* emb = (const float*)d_in[1];
    const float* W1  = (const float*)d_in[2];
    const float* b1  = (const float*)d_in[3];
    const float* W2  = (const float*)d_in[4];
    const float* b2  = (const float*)d_in[5];
    float* out = (float*)d_out;

    fused_kernel<<<512, 256>>>(x, emb, W1, b1, W2, b2, out);
}

// round 15
// speedup vs baseline: 1.3111x; 1.3111x over previous
#include <cuda_runtime.h>

#define B_      16
#define D_      64
#define N_      256
#define E_      64
#define HID_    128
#define OUT_    64
#define IN_     192
#define R_PAIRS 32640
#define UV_PAD  18

typedef unsigned long long ull;

// Cross-block scratch
__device__ float    g_S[B_ * HID_];
__device__ unsigned g_done[B_];

// ---- dynamic smem layout (bytes) ----
#define OFF_WT   0                      // 2048 ull  = 16384
#define OFF_US   16384                  // 256*18 f  = 18432
#define OFF_VS   34816                  // 256*18 f  = 18432
#define OFF_CS   53248                  // 16 f      = 64
#define OFF_LR   53312                  // 64 f      = 256
#define OFF_RED  53568                  // 32*8 f2   = 2048
#define OFF_SS   55616                  // 128 f     = 512
#define SMEM_TOT 56128

// ---------------- packed f32x2 helpers ----------------
__device__ __forceinline__ void fma2(ull& acc, ull w, ull x) {
    asm("fma.rn.f32x2 %0, %1, %2, %3;" : "=l"(acc) : "l"(w), "l"(x), "l"(acc));
}
__device__ __forceinline__ ull pack2(float a, float b) {
    ull r;
    asm("mov.b64 %0, {%1, %2};" : "=l"(r) : "f"(a), "f"(b));
    return r;
}
__device__ __forceinline__ float lo2(ull v) {
    return __uint_as_float((unsigned)(v & 0xffffffffu));
}
__device__ __forceinline__ float hi2(ull v) {
    return __uint_as_float((unsigned)(v >> 32));
}
__device__ __forceinline__ ull padd2(ull a, ull b) {
    ull r;
    asm("add.rn.f32x2 %0, %1, %2;" : "=l"(r) : "l"(a), "l"(b));
    return r;
}
__device__ __forceinline__ void addabs2(ull& acc, ull t2, ull v2, ull mask) {
    ull x;
    asm("add.rn.f32x2 %0, %1, %2;" : "=l"(x) : "l"(t2), "l"(v2));
    asm("and.b64 %0, %1, %2;" : "=l"(x) : "l"(x), "l"(mask));
    asm("add.rn.f32x2 %0, %1, %2;" : "=l"(acc) : "l"(acc), "l"(x));
}

// ===========================================================================
// grid = 128 = (b:16, hg:8 -> 16 h each); block = 1024 (32 warps), ~55 KB smem.
// ===========================================================================
__global__ __launch_bounds__(1024, 1) void fused_kernel(
    const float* __restrict__ x, const float* __restrict__ emb,
    const float* __restrict__ W1, const float* __restrict__ b1,
    const float* __restrict__ W2, const float* __restrict__ b2,
    float* __restrict__ out)
{
    extern __shared__ __align__(16) char smem[];
    ull*    wt  = (ull*)(smem + OFF_WT);     // [16h][2ab][64d] dup-packed
    float*  us  = (float*)(smem + OFF_US);   // [256 n][18]
    float*  vs  = (float*)(smem + OFF_VS);
    float*  cs  = (float*)(smem + OFF_CS);   // [16]
    float*  lr  = (float*)(smem + OFF_LR);   // [16h][4nq]
    float2* red = (float2*)(smem + OFF_RED); // [32w][8hp]
    float*  Ss  = (float*)(smem + OFF_SS);   // [128]
    __shared__ bool lastf;

    const int bx    = blockIdx.x;
    const int hg    = bx & 7;
    const int b     = bx >> 3;
    const int hbase = hg * 16;
    const int tid   = threadIdx.x;
    const int w     = tid >> 5;
    const int lane  = tid & 31;

    // ---- duplicated W table: wt[hl*128 + ab*64 + d] = (W,W) ----
#pragma unroll
    for (int i = 0; i < 2; ++i) {
        int idx = i * 1024 + tid;
        int hl  = idx >> 7;
        int ab  = (idx >> 6) & 1;
        int d   = idx & 63;
        float wv = W1[(hbase + hl) * IN_ + ab * 64 + d];
        wt[idx] = pack2(wv, wv);
    }
    // ---- C for these 16 h ----
    if (tid < 16) {
        int h = hbase + tid;
        const float4* wr = (const float4*)(W1 + h * IN_ + 2 * D_);
        const float4* er = (const float4*)(emb + b * E_);
        float acc = b1[h];
#pragma unroll
        for (int e4 = 0; e4 < E_ / 4; ++e4) {
            float4 ww = wr[e4]; float4 ee = er[e4];
            acc += ww.x * ee.x + ww.y * ee.y + ww.z * ee.z + ww.w * ee.w;
        }
        cs[tid] = acc;
    }
    __syncthreads();

    // ===== Phase A: warp = (h2: w&7 -> 2 h, nq: w>>3 -> 64 n), n-packed ======
    {
        const int h2 = w & 7;
        const int nq = w >> 3;
        const int n0 = nq * 64 + 2 * lane;
        const int h0 = 2 * h2, h1 = 2 * h2 + 1;
        const float* xp = x + b * D_ * N_ + n0;
        const ulonglong2* wAe = (const ulonglong2*)(wt + h0 * 128);
        const ulonglong2* wBe = (const ulonglong2*)(wt + h0 * 128 + 64);
        const ulonglong2* wAo = (const ulonglong2*)(wt + h1 * 128);
        const ulonglong2* wBo = (const ulonglong2*)(wt + h1 * 128 + 64);

        ull au0 = 0, av0 = 0, au1 = 0, av1 = 0;
#pragma unroll 8
        for (int d2 = 0; d2 < 32; ++d2) {
            ull x0 = *(const ull*)(xp + (2 * d2) * N_);
            ull x1 = *(const ull*)(xp + (2 * d2 + 1) * N_);
            ulonglong2 Ae = wAe[d2], Be = wBe[d2];
            ulonglong2 Ao = wAo[d2], Bo = wBo[d2];
            fma2(au0, Ae.x, x0); fma2(au0, Ae.y, x1);
            fma2(av0, Be.x, x0); fma2(av0, Be.y, x1);
            fma2(au1, Ao.x, x0); fma2(au1, Ao.y, x1);
            fma2(av1, Bo.x, x0); fma2(av1, Bo.y, x1);
        }

        us[n0 * UV_PAD + h0]       = lo2(au0);
        us[(n0 + 1) * UV_PAD + h0] = hi2(au0);
        us[n0 * UV_PAD + h1]       = lo2(au1);
        us[(n0 + 1) * UV_PAD + h1] = hi2(au1);
        vs[n0 * UV_PAD + h0]       = lo2(av0);
        vs[(n0 + 1) * UV_PAD + h0] = hi2(av0);
        vs[n0 * UV_PAD + h1]       = lo2(av1);
        vs[(n0 + 1) * UV_PAD + h1] = hi2(av1);

        float nf = (float)n0;
        float lin0 = lo2(au0) * (255.0f - nf) + lo2(av0) * nf
                   + hi2(au0) * (254.0f - nf) + hi2(av0) * (nf + 1.0f);
        float lin1 = lo2(au1) * (255.0f - nf) + lo2(av1) * nf
                   + hi2(au1) * (254.0f - nf) + hi2(av1) * (nf + 1.0f);
#pragma unroll
        for (int o = 16; o; o >>= 1) {
            lin0 += __shfl_xor_sync(0xffffffffu, lin0, o);
            lin1 += __shfl_xor_sync(0xffffffffu, lin1, o);
        }
        if (lane == 0) {
            lr[h0 * 4 + nq] = lin0;
            lr[h1 * 4 + nq] = lin1;
        }
    }
    __syncthreads();

    // ===== Phase B: warp = (tp: w&15 -> tiles {tp,31-tp}, jh: w>>4) ==========
    {
        const ull mask = 0x7FFFFFFF7FFFFFFFull;
        const int tp   = w & 15;
        const int jh   = w >> 4;
        const int hp   = lane & 7;
        const int isub = lane >> 3;               // 0..3 -> i pair

        ull ccp;
        { float2 c2 = *(const float2*)(cs + 2 * hp); ccp = pack2(c2.x, c2.y); }

        ull a0 = 0, a1 = 0, a2 = 0, a3 = 0;
#pragma unroll
        for (int rep = 0; rep < 2; ++rep) {
            int tile = rep ? (31 - tp) : tp;
            int i0   = tile * 8;
            int ia   = i0 + 2 * isub;

            ull ua = *(const ull*)(us + ia * UV_PAD + 2 * hp);
            ull ub = *(const ull*)(us + (ia + 1) * UV_PAD + 2 * hp);
            ull tA = padd2(ua, ccp);
            ull tB = padd2(ub, ccp);

            // triangular corner: jh==0 warps only (count once)
            if (jh == 0) {
#pragma unroll
                for (int jj = 1; jj < 8; ++jj) {
                    ull vj = *(const ull*)(vs + (i0 + jj) * UV_PAD + 2 * hp);
                    if (2 * isub < jj)     addabs2(a0, tA, vj, mask);
                    if (2 * isub + 1 < jj) addabs2(a1, tB, vj, mask);
                }
            }

            int len  = 248 - 8 * tile;            // multiple of 8 (0 for tile 31)
            int half = len >> 1;                  // multiple of 4
            int jlo  = i0 + 8 + jh * half;
            int jhi  = jlo + half;
            const float* vb = vs + 2 * hp;
            for (int j = jlo; j < jhi; j += 4) {
                ull v0 = *(const ull*)(vb + (j + 0) * UV_PAD);
                ull v1 = *(const ull*)(vb + (j + 1) * UV_PAD);
                ull v2 = *(const ull*)(vb + (j + 2) * UV_PAD);
                ull v3 = *(const ull*)(vb + (j + 3) * UV_PAD);
                addabs2(a0, tA, v0, mask); addabs2(a1, tB, v0, mask);
                addabs2(a2, tA, v1, mask); addabs2(a3, tB, v1, mask);
                addabs2(a0, tA, v2, mask); addabs2(a1, tB, v2, mask);
                addabs2(a2, tA, v3, mask); addabs2(a3, tB, v3, mask);
            }
        }

        ull s2 = padd2(padd2(a0, a1), padd2(a2, a3));
        float sx = lo2(s2), sy = hi2(s2);
        sx += __shfl_xor_sync(0xffffffffu, sx, 8);
        sx += __shfl_xor_sync(0xffffffffu, sx, 16);
        sy += __shfl_xor_sync(0xffffffffu, sy, 8);
        sy += __shfl_xor_sync(0xffffffffu, sy, 16);
        if (lane < 8) red[w * 8 + hp] = make_float2(sx, sy);
    }
    __syncthreads();

    // ===== combine: S[b][hbase..hbase+15] =====
    if (tid < 16) {
        int h  = tid;
        int hp = h >> 1;
        int c  = h & 1;
        float sabs = 0.0f;
#pragma unroll
        for (int ww = 0; ww < 32; ++ww) {
            float2 r = red[ww * 8 + hp];
            sabs += c ? r.y : r.x;
        }
        float lin = (lr[h * 4 + 0] + lr[h * 4 + 1]) + (lr[h * 4 + 2] + lr[h * 4 + 3]);
        lin += cs[h] * (float)R_PAIRS;
        g_S[b * HID_ + hbase + h] = 0.5f * (lin + sabs);
    }

    // ===== completion: last of 8 blocks per b does the out GEMM =====
    __syncthreads();
    if (tid == 0) {
        __threadfence();
        unsigned v = atomicAdd(&g_done[b], 1u);
        lastf = (v == 7u);
        if (v == 7u) {
            g_done[b] = 0;          // reset for next graph replay
            __threadfence();
        }
    }
    __syncthreads();

    if (lastf) {
        if (tid < HID_) Ss[tid] = g_S[b * HID_ + tid];
        __syncthreads();
        // 1024 threads: o = tid>>4 (64 outputs), 16 lanes x 8 h each
        int o   = tid >> 4;
        int sub = tid & 15;
        const float4* wv = (const float4*)(W2 + o * HID_ + sub * 8);
        const float4* sv = (const float4*)(Ss + sub * 8);
        float4 w0 = wv[0], w1 = wv[1];
        float4 s0 = sv[0], s1 = sv[1];
        float acc = w0.x * s0.x + w0.y * s0.y + w0.z * s0.z + w0.w * s0.w
                  + w1.x * s1.x + w1.y * s1.y + w1.z * s1.z + w1.w * s1.w;
#pragma unroll
        for (int off = 8; off; off >>= 1)
            acc += __shfl_xor_sync(0xffffffffu, acc, off);
        if (sub == 0)
            out[b * OUT_ + o] = acc + (float)R_PAIRS * b2[o];
    }
}

// ---------------------------------------------------------------------------
extern "C" void kernel_launch(void* const* d_in, const int* in_sizes, int n_in,
                              void* d_out, int out_size) {
    const float* x   = (const float*)d_in[0];
    const float* emb = (const float*)d_in[1];
    const float* W1  = (const float*)d_in[2];
    const float* b1  = (const float*)d_in[3];
    const float* W2  = (const float*)d_in[4];
    const float* b2  = (const float*)d_in[5];
    float* out = (float*)d_out;

    cudaFuncSetAttribute(fused_kernel,
                         cudaFuncAttributeMaxDynamicSharedMemorySize, SMEM_TOT);
    fused_kernel<<<128, 1024, SMEM_TOT>>>(x, emb, W1, b1, W2, b2, out);
}